// round 16
// baseline (speedup 1.0000x reference)
#include <cuda_runtime.h>
#include <cuda_fp16.h>
#include <math.h>
#include <cstdint>

// Scratch (allocation-free rule: __device__ globals)
__device__ __half g_qh[4096 * 1024];     // Q fp16 (pre-scaled by 0.125)
__device__ __half g_kh[4096 * 1024];     // K fp16
__device__ __half g_vh[4096 * 1024];     // V fp16
__device__ __half g_yh[4096 * 1024];     // attention output, fp16
__device__ __half g_xh[4096 * 1024];     // fp16 x
__device__ __half g_wqkvh[1024 * 3072];  // fp16 w_qkv
__device__ __half g_wouth[1024 * 1024];  // fp16 w_out

// ---------------------------------------------------------------------------
// Helpers
// ---------------------------------------------------------------------------
__device__ __forceinline__ uint32_t smem_u32(const void* p) {
    uint32_t a;
    asm("{ .reg .u64 t; cvta.to.shared.u64 t, %1; cvt.u32.u64 %0, t; }"
        : "=r"(a) : "l"(p));
    return a;
}
__device__ __forceinline__ void cp_async16(uint32_t dst, const void* src) {
    asm volatile("cp.async.cg.shared.global [%0], [%1], 16;" :: "r"(dst), "l"(src));
}
__device__ __forceinline__ void cp_commit() {
    asm volatile("cp.async.commit_group;");
}
__device__ __forceinline__ void mma_f16_16x8x16(
    float* c, const uint32_t* a, const uint32_t* b) {
    asm volatile(
        "mma.sync.aligned.m16n8k16.row.col.f32.f16.f16.f32 "
        "{%0,%1,%2,%3}, {%4,%5,%6,%7}, {%8,%9}, {%0,%1,%2,%3};"
        : "+f"(c[0]), "+f"(c[1]), "+f"(c[2]), "+f"(c[3])
        : "r"(a[0]), "r"(a[1]), "r"(a[2]), "r"(a[3]), "r"(b[0]), "r"(b[1]));
}
__device__ __forceinline__ void ldmx4(uint32_t* r, uint32_t addr) {
    asm volatile("ldmatrix.sync.aligned.m8n8.x4.shared.b16 {%0,%1,%2,%3}, [%4];"
        : "=r"(r[0]), "=r"(r[1]), "=r"(r[2]), "=r"(r[3]) : "r"(addr));
}
__device__ __forceinline__ void ldmx4t(uint32_t* r, uint32_t addr) {
    asm volatile("ldmatrix.sync.aligned.m8n8.x4.trans.shared.b16 {%0,%1,%2,%3}, [%4];"
        : "=r"(r[0]), "=r"(r[1]), "=r"(r[2]), "=r"(r[3]) : "r"(addr));
}
// pack(lo, hi) -> b32 half2 {lo in [15:0], hi in [31:16]}
__device__ __forceinline__ uint32_t packh2(float lo, float hi) {
    uint32_t d;
    asm("cvt.rn.f16x2.f32 %0, %1, %2;" : "=r"(d) : "f"(hi), "f"(lo));
    return d;
}
// packed 2^x on half2
__device__ __forceinline__ uint32_t h2ex2(uint32_t x) {
    uint32_t d;
    asm("ex2.approx.f16x2 %0, %1;" : "=r"(d) : "r"(x));
    return d;
}

// ---------------------------------------------------------------------------
// Fused prepass: f32 -> f16 for x, w_qkv, w_out in one launch.
// ---------------------------------------------------------------------------
#define N4_X  (4096 * 1024 / 4)
#define N4_WQ (1024 * 3072 / 4)
#define N4_WO (1024 * 1024 / 4)

__global__ __launch_bounds__(256) void to_half3(
    const float* __restrict__ x,  __half* __restrict__ dx,
    const float* __restrict__ wq, __half* __restrict__ dwq,
    const float* __restrict__ wo, __half* __restrict__ dwo)
{
    const int total = N4_X + N4_WQ + N4_WO;
    int stride = gridDim.x * blockDim.x;
    for (int i = blockIdx.x * blockDim.x + threadIdx.x; i < total; i += stride) {
        const float* s;
        __half* d;
        int j = i;
        if (j < N4_X)            { s = x;  d = dx; }
        else if (j < N4_X+N4_WQ) { s = wq; d = dwq; j -= N4_X; }
        else                     { s = wo; d = dwo; j -= N4_X + N4_WQ; }
        float4 v = ((const float4*)s)[j];
        uint2 o;
        o.x = packh2(v.x, v.y);
        o.y = packh2(v.z, v.w);
        ((uint2*)d)[j] = o;
    }
}

// ---------------------------------------------------------------------------
// fp16 GEMM, 128x96 CTA tile (QKV path).  Warp grid 4(M)x2(N), warp tile
// 32x48 = 2 mf x 6 nf.  B smem [64][104]h.  Epilogue writes Q (x0.125) /
// K / V f16 planes.
// ---------------------------------------------------------------------------
#define G96A_H (128 * 72)
#define G96B_H (64 * 104)
#define G96S_H (G96A_H + G96B_H)
#define GEMM96_SMEM (3 * G96S_H * 2)        // 95,232 B

__global__ __launch_bounds__(256, 2)
void gemm_qkv96(const __half* __restrict__ A, const __half* __restrict__ B,
                const float* __restrict__ bias,
                __half* qh, __half* kh, __half* vh)
{
    extern __shared__ __align__(16) __half smh[];
    const int K = 1024, N = 3072;

    const int tid = threadIdx.x;
    const int wid = tid >> 5, lane = tid & 31;
    const int m0 = blockIdx.x * 128;
    const int n0 = blockIdx.y * 96;
    const int wm = wid & 3;                  // m offset wm*32
    const int wn = wid >> 2;                 // n offset wn*48

    const uint32_t sbase = smem_u32(smh);

    auto prefetch = [&](int k0, int stage) {
        uint32_t Ad = sbase + stage * G96S_H * 2;
        uint32_t Bd = Ad + G96A_H * 2;
        #pragma unroll
        for (int i = 0; i < 4; i++) {        // A: 128 rows x 8 segs
            int s = tid + i * 256;
            int r = s >> 3, seg = s & 7;
            cp_async16(Ad + (r * 72 + seg * 8) * 2,
                       A + (size_t)(m0 + r) * K + k0 + seg * 8);
        }
        #pragma unroll
        for (int i = 0; i < 3; i++) {        // B: 64 rows x 12 segs = 768
            int s = tid + i * 256;
            int r = s / 12, seg = s % 12;
            cp_async16(Bd + (r * 104 + seg * 8) * 2,
                       B + (size_t)(k0 + r) * N + n0 + seg * 8);
        }
        cp_commit();
    };

    float acc[2][6][4];
    #pragma unroll
    for (int i = 0; i < 2; i++)
        #pragma unroll
        for (int j = 0; j < 6; j++)
            #pragma unroll
            for (int r = 0; r < 4; r++) acc[i][j][r] = 0.f;

    const int NCH = K >> 6;
    prefetch(0, 0);
    prefetch(64, 1);

    const int l15 = lane & 15;
    const uint32_t koff16 = (lane & 16) ? 8 : 0;

    for (int c = 0; c < NCH; c++) {
        if (c == NCH - 1)
            asm volatile("cp.async.wait_group 0;" ::: "memory");
        else
            asm volatile("cp.async.wait_group 1;" ::: "memory");
        __syncthreads();

        if (c + 2 < NCH) prefetch((c + 2) * 64, (c + 2) % 3);

        const uint32_t Asm = sbase + (c % 3) * G96S_H * 2;
        const uint32_t Bsm = Asm + G96A_H * 2;

        #pragma unroll
        for (int ks = 0; ks < 4; ks++) {
            const int kb = ks * 16;
            uint32_t af[2][4], bf[6][2];
            #pragma unroll
            for (int mf = 0; mf < 2; mf++)
                ldmx4(af[mf], Asm + ((wm * 32 + mf * 16 + l15) * 72 + kb + koff16) * 2);
            #pragma unroll
            for (int nfp = 0; nfp < 3; nfp++) {
                uint32_t t[4];
                ldmx4t(t, Bsm + ((kb + l15) * 104 + wn * 48 + nfp * 16 + koff16) * 2);
                bf[2 * nfp][0] = t[0]; bf[2 * nfp][1] = t[1];
                bf[2 * nfp + 1][0] = t[2]; bf[2 * nfp + 1][1] = t[3];
            }
            #pragma unroll
            for (int mf = 0; mf < 2; mf++)
                #pragma unroll
                for (int nf = 0; nf < 6; nf++)
                    mma_f16_16x8x16(acc[mf][nf], af[mf], bf[nf]);
        }
        __syncthreads();
    }

    const int lr = lane >> 2;
    const int lc = lane & 3;
    #pragma unroll
    for (int mf = 0; mf < 2; mf++) {
        int row = m0 + wm * 32 + mf * 16 + lr;
        #pragma unroll
        for (int nf = 0; nf < 6; nf++) {
            int col = n0 + wn * 48 + nf * 8 + 2 * lc;
            float b0 = bias[col], b1 = bias[col + 1];
            float v00 = acc[mf][nf][0] + b0, v01 = acc[mf][nf][1] + b1;
            float v10 = acc[mf][nf][2] + b0, v11 = acc[mf][nf][3] + b1;
            if (col < 1024) {                  // Q plane, fold 1/sqrt(hd)
                *(uint32_t*)&qh[(size_t)row * 1024 + col] =
                    packh2(v00 * 0.125f, v01 * 0.125f);
                *(uint32_t*)&qh[(size_t)(row + 8) * 1024 + col] =
                    packh2(v10 * 0.125f, v11 * 0.125f);
            } else if (col < 2048) {           // K plane
                *(uint32_t*)&kh[(size_t)row * 1024 + col - 1024] = packh2(v00, v01);
                *(uint32_t*)&kh[(size_t)(row + 8) * 1024 + col - 1024] = packh2(v10, v11);
            } else {                           // V plane
                *(uint32_t*)&vh[(size_t)row * 1024 + col - 2048] = packh2(v00, v01);
                *(uint32_t*)&vh[(size_t)(row + 8) * 1024 + col - 2048] = packh2(v10, v11);
            }
        }
    }
}

// ---------------------------------------------------------------------------
// fp16 GEMM 128x64 + bias -> f32 C (out-projection).
// Round-16: 512 CTAs (vs 256 at 128x128) halves the work-steal granularity;
// per-element accumulation chain order unchanged -> bit-identical output.
// Warp grid 4(M)x2(N), warp tile 32x32 = 2 mf x 4 nf.  B smem [64][72]h.
// ---------------------------------------------------------------------------
#define O64A_H (128 * 72)
#define O64B_H (64 * 72)
#define O64S_H (O64A_H + O64B_H)
#define OUT64_SMEM (3 * O64S_H * 2)         // 82,944 B

__global__ __launch_bounds__(256, 2)
void gemm_out64(const __half* __restrict__ A, const __half* __restrict__ B,
                const float* __restrict__ bias, float* __restrict__ C)
{
    extern __shared__ __align__(16) __half smh[];
    const int K = 1024, N = 1024;

    const int tid = threadIdx.x;
    const int wid = tid >> 5, lane = tid & 31;
    const int m0 = blockIdx.x * 128;
    const int n0 = blockIdx.y * 64;
    const int wm = wid & 3;                  // m offset wm*32
    const int wn = wid >> 2;                 // n offset wn*32

    const uint32_t sbase = smem_u32(smh);

    auto prefetch = [&](int k0, int stage) {
        uint32_t Ad = sbase + stage * O64S_H * 2;
        uint32_t Bd = Ad + O64A_H * 2;
        #pragma unroll
        for (int i = 0; i < 4; i++) {        // A: 128 rows x 8 segs
            int s = tid + i * 256;
            int r = s >> 3, seg = s & 7;
            cp_async16(Ad + (r * 72 + seg * 8) * 2,
                       A + (size_t)(m0 + r) * K + k0 + seg * 8);
        }
        #pragma unroll
        for (int i = 0; i < 2; i++) {        // B: 64 rows x 8 segs = 512
            int s = tid + i * 256;
            int r = s >> 3, seg = s & 7;
            cp_async16(Bd + (r * 72 + seg * 8) * 2,
                       B + (size_t)(k0 + r) * N + n0 + seg * 8);
        }
        cp_commit();
    };

    float acc[2][4][4];
    #pragma unroll
    for (int i = 0; i < 2; i++)
        #pragma unroll
        for (int j = 0; j < 4; j++)
            #pragma unroll
            for (int r = 0; r < 4; r++) acc[i][j][r] = 0.f;

    const int NCH = K >> 6;
    prefetch(0, 0);
    prefetch(64, 1);

    const int l15 = lane & 15;
    const uint32_t koff16 = (lane & 16) ? 8 : 0;

    for (int c = 0; c < NCH; c++) {
        if (c == NCH - 1)
            asm volatile("cp.async.wait_group 0;" ::: "memory");
        else
            asm volatile("cp.async.wait_group 1;" ::: "memory");
        __syncthreads();

        if (c + 2 < NCH) prefetch((c + 2) * 64, (c + 2) % 3);

        const uint32_t Asm = sbase + (c % 3) * O64S_H * 2;
        const uint32_t Bsm = Asm + O64A_H * 2;

        #pragma unroll
        for (int ks = 0; ks < 4; ks++) {
            const int kb = ks * 16;
            uint32_t af[2][4], bf[4][2];
            #pragma unroll
            for (int mf = 0; mf < 2; mf++)
                ldmx4(af[mf], Asm + ((wm * 32 + mf * 16 + l15) * 72 + kb + koff16) * 2);
            #pragma unroll
            for (int nfp = 0; nfp < 2; nfp++) {
                uint32_t t[4];
                ldmx4t(t, Bsm + ((kb + l15) * 72 + wn * 32 + nfp * 16 + koff16) * 2);
                bf[2 * nfp][0] = t[0]; bf[2 * nfp][1] = t[1];
                bf[2 * nfp + 1][0] = t[2]; bf[2 * nfp + 1][1] = t[3];
            }
            #pragma unroll
            for (int mf = 0; mf < 2; mf++)
                #pragma unroll
                for (int nf = 0; nf < 4; nf++)
                    mma_f16_16x8x16(acc[mf][nf], af[mf], bf[nf]);
        }
        __syncthreads();
    }

    const int lr = lane >> 2;
    const int lc = lane & 3;
    #pragma unroll
    for (int mf = 0; mf < 2; mf++) {
        int row = m0 + wm * 32 + mf * 16 + lr;
        #pragma unroll
        for (int nf = 0; nf < 4; nf++) {
            int col = n0 + wn * 32 + nf * 8 + 2 * lc;
            float b0 = bias[col], b1 = bias[col + 1];
            *(float2*)&C[(size_t)row * N + col] =
                make_float2(acc[mf][nf][0] + b0, acc[mf][nf][1] + b1);
            *(float2*)&C[(size_t)(row + 8) * N + col] =
                make_float2(acc[mf][nf][2] + b0, acc[mf][nf][3] + b1);
        }
    }
}

// ---------------------------------------------------------------------------
// Causal flash attention, all-fp16 tensor ops (unchanged from round 15).
// smem halves: Q[128][72], K ring3[64][72], V ring3[64][72] = 73,728 B.
// ---------------------------------------------------------------------------
#define ATTN_SMEM 73728
#define LOG2E 1.4426950408889634f

__global__ __launch_bounds__(256, 2)
void attn_tc(const __half* __restrict__ qh_g, const __half* __restrict__ kh_g,
             const __half* __restrict__ v_g,  __half* __restrict__ y)
{
    extern __shared__ __align__(16) __half smh[];

    const int bh = blockIdx.x;                   // 0..31
    const int qt = 15 - blockIdx.y;              // heavy tiles first
    const int b = bh >> 4, h = bh & 15;
    const int tid = threadIdx.x;
    const int wid = tid >> 5, lane = tid & 31;
    const int lr = lane >> 2, lc = lane & 3;
    const int l15 = lane & 15;
    const uint32_t koff16 = (lane & 16) ? 8 : 0;
    const uint32_t koff8  = (lane & 8)  ? 8 : 0;
    const int l7 = lane & 7;
    const int q0 = qt * 128;
    const int rowbase = b * 2048;
    const int colq = h * 64;

    const uint32_t sbase = smem_u32(smh);
    const uint32_t QA = sbase;                   // 128*72 h
    const uint32_t KA = QA + 128 * 72 * 2;       // 3 x 64*72 h
    const uint32_t VA = KA + 3 * 64 * 72 * 2;    // 3 x 64*72 h

    // Async-load Q tile (own commit group; completed by first wait at kt=0)
    #pragma unroll
    for (int j = 0; j < 4; j++) {
        int s = tid + j * 256;
        int r = s >> 3, seg = s & 7;
        cp_async16(QA + (r * 72 + seg * 8) * 2,
                   qh_g + (size_t)(rowbase + q0 + r) * 1024 + colq + seg * 8);
    }
    cp_commit();

    auto prefetch = [&](int kt) {
        const int buf = kt % 3;
        const uint32_t Kd = KA + buf * (64 * 72 * 2);
        const uint32_t Vd = VA + buf * (64 * 72 * 2);
        #pragma unroll
        for (int j = 0; j < 2; j++) {
            int s = tid + j * 256;
            int r = s >> 3, seg = s & 7;
            size_t g = (size_t)(rowbase + kt * 64 + r) * 1024 + colq + seg * 8;
            cp_async16(Kd + (r * 72 + seg * 8) * 2, kh_g + g);
            cp_async16(Vd + (r * 72 + seg * 8) * 2, v_g  + g);
        }
        cp_commit();
    };

    const int ktmax = 2 * qt + 1;                // >= 1 always
    prefetch(0);
    prefetch(1);

    float m_i[2] = {-INFINITY, -INFINITY};
    float l_i[2] = {0.f, 0.f};
    float acc_o[8][4];
    #pragma unroll
    for (int nf = 0; nf < 8; nf++)
        #pragma unroll
        for (int c = 0; c < 4; c++) acc_o[nf][c] = 0.f;

    const int r_row = 16 * wid + lr;

    for (int kt = 0; kt <= ktmax; kt++) {
        if (kt < ktmax)
            asm volatile("cp.async.wait_group 1;" ::: "memory");
        else
            asm volatile("cp.async.wait_group 0;" ::: "memory");
        __syncthreads();     // tile kt (and Q at kt=0) ready; buf (kt+2)%3 free

        if (kt + 2 <= ktmax) prefetch(kt + 2);

        // Odd diagonal tile: rows < 64 (warps 0-3) are entirely masked.
        if (kt == ktmax && wid < 4) continue;

        // Fragment-level diag limit (warp-uniform).
        const int lim = (kt >= 2 * qt) ? (wid - ((kt - 2 * qt) << 2)) : 3;

        const uint32_t KB = KA + (kt % 3) * (64 * 72 * 2);
        const uint32_t VB = VA + (kt % 3) * (64 * 72 * 2);

        // ---- S = Q K^T : plain fp16, ldmatrix frags ----
        float sacc[8][4];
        #pragma unroll
        for (int nf = 0; nf < 8; nf++)
            #pragma unroll
            for (int c = 0; c < 4; c++) sacc[nf][c] = 0.f;

        #pragma unroll
        for (int ks = 0; ks < 4; ks++) {
            const int kb = ks * 16;
            uint32_t ah[4];
            ldmx4(ah, QA + ((16 * wid + l15) * 72 + kb + koff16) * 2);
            #pragma unroll
            for (int nfp = 0; nfp < 4; nfp++) {
                if (nfp <= lim) {
                    uint32_t bh2[4];
                    ldmx4(bh2, KB + ((16 * nfp + l7 + koff16) * 72 + kb + koff8) * 2);
                    mma_f16_16x8x16(sacc[2 * nfp],     ah, bh2);
                    mma_f16_16x8x16(sacc[2 * nfp + 1], ah, bh2 + 2);
                }
            }
        }

        // ---- Causal mask (only the 2 diagonal k-tiles) ----
        if (kt >= 2 * qt) {
            const int rg = q0 + r_row;
            const int cb0 = kt * 64 + 2 * lc;
            #pragma unroll
            for (int nf = 0; nf < 8; nf++) {
                int c0 = cb0 + 8 * nf;
                if (c0     > rg)     sacc[nf][0] = -INFINITY;
                if (c0 + 1 > rg)     sacc[nf][1] = -INFINITY;
                if (c0     > rg + 8) sacc[nf][2] = -INFINITY;
                if (c0 + 1 > rg + 8) sacc[nf][3] = -INFINITY;
            }
        }

        // ---- Online softmax: max update + packed exp2 ----
        float tm0 = -INFINITY, tm1 = -INFINITY;
        #pragma unroll
        for (int nf = 0; nf < 8; nf++) {
            tm0 = fmaxf(tm0, fmaxf(sacc[nf][0], sacc[nf][1]));
            tm1 = fmaxf(tm1, fmaxf(sacc[nf][2], sacc[nf][3]));
        }
        tm0 = fmaxf(tm0, __shfl_xor_sync(0xffffffffu, tm0, 1));
        tm0 = fmaxf(tm0, __shfl_xor_sync(0xffffffffu, tm0, 2));
        tm1 = fmaxf(tm1, __shfl_xor_sync(0xffffffffu, tm1, 1));
        tm1 = fmaxf(tm1, __shfl_xor_sync(0xffffffffu, tm1, 2));

        const float nm0 = fmaxf(m_i[0], tm0);
        const float nm1 = fmaxf(m_i[1], tm1);
        const float sc0 = __expf(m_i[0] - nm0);
        const float sc1 = __expf(m_i[1] - nm1);
        m_i[0] = nm0;
        m_i[1] = nm1;
        const float nmL0 = nm0 * LOG2E, nmL1 = nm1 * LOG2E;

        // P packed as half2 exp2((s-m)*log2e): this IS the PV A-frag.
        uint32_t pfr[8][2];
        #pragma unroll
        for (int nf = 0; nf < 8; nf++) {
            pfr[nf][0] = h2ex2(packh2(fmaf(sacc[nf][0], LOG2E, -nmL0),
                                      fmaf(sacc[nf][1], LOG2E, -nmL0)));
            pfr[nf][1] = h2ex2(packh2(fmaf(sacc[nf][2], LOG2E, -nmL1),
                                      fmaf(sacc[nf][3], LOG2E, -nmL1)));
        }

        // ---- Row-sum l from the SAME f16 p values, in f32 (FMA pipe) ----
        float rs0 = 0.f, rs1 = 0.f;
        #pragma unroll
        for (int nf = 0; nf < 8; nf++) {
            float2 p0 = __half22float2(*(const __half2*)&pfr[nf][0]);
            float2 p1 = __half22float2(*(const __half2*)&pfr[nf][1]);
            rs0 += p0.x + p0.y;
            rs1 += p1.x + p1.y;
        }
        rs0 += __shfl_xor_sync(0xffffffffu, rs0, 1);
        rs0 += __shfl_xor_sync(0xffffffffu, rs0, 2);
        rs1 += __shfl_xor_sync(0xffffffffu, rs1, 1);
        rs1 += __shfl_xor_sync(0xffffffffu, rs1, 2);
        l_i[0] = l_i[0] * sc0 + rs0;
        l_i[1] = l_i[1] * sc1 + rs1;

        // Rescale O accumulators
        #pragma unroll
        for (int nf = 0; nf < 8; nf++) {
            acc_o[nf][0] *= sc0; acc_o[nf][1] *= sc0;
            acc_o[nf][2] *= sc1; acc_o[nf][3] *= sc1;
        }

        // ---- O += P V  (skip key-chunks with all-zero P on diag tiles) ----
        #pragma unroll
        for (int ks = 0; ks < 4; ks++) {
            if (ks <= lim) {
                uint32_t pa[4];
                pa[0] = pfr[2 * ks][0];
                pa[1] = pfr[2 * ks][1];
                pa[2] = pfr[2 * ks + 1][0];
                pa[3] = pfr[2 * ks + 1][1];
                #pragma unroll
                for (int nfp = 0; nfp < 4; nfp++) {
                    uint32_t tv[4];
                    ldmx4t(tv, VB + ((16 * ks + l7 + koff8) * 72 + 16 * nfp + koff16) * 2);
                    mma_f16_16x8x16(acc_o[2 * nfp],     pa, tv);
                    mma_f16_16x8x16(acc_o[2 * nfp + 1], pa, tv + 2);
                }
            }
        }
    }

    // ---- Epilogue: normalize, store y as f16 (out-proj A operand) ----
    const float il0 = 1.f / l_i[0];
    const float il1 = 1.f / l_i[1];
    const size_t row0 = (size_t)(rowbase + q0 + r_row) * 1024;
    const size_t row1 = row0 + 8 * 1024;
    #pragma unroll
    for (int nf = 0; nf < 8; nf++) {
        int col = colq + 8 * nf + 2 * lc;
        *(uint32_t*)&y[row0 + col] = packh2(acc_o[nf][0] * il0, acc_o[nf][1] * il0);
        *(uint32_t*)&y[row1 + col] = packh2(acc_o[nf][2] * il1, acc_o[nf][3] * il1);
    }
}

// ---------------------------------------------------------------------------
extern "C" void kernel_launch(void* const* d_in, const int* in_sizes, int n_in,
                              void* d_out, int out_size)
{
    const float* x     = (const float*)d_in[0];
    const float* w_qkv = (const float*)d_in[1];
    const float* b_qkv = (const float*)d_in[2];
    const float* w_out = (const float*)d_in[3];
    const float* b_out = (const float*)d_in[4];
    float* out = (float*)d_out;

    __half *qh, *kh, *vh, *yh, *xh, *wqh, *woh;
    cudaGetSymbolAddress((void**)&qh,  g_qh);
    cudaGetSymbolAddress((void**)&kh,  g_kh);
    cudaGetSymbolAddress((void**)&vh,  g_vh);
    cudaGetSymbolAddress((void**)&yh,  g_yh);
    cudaGetSymbolAddress((void**)&xh,  g_xh);
    cudaGetSymbolAddress((void**)&wqh, g_wqkvh);
    cudaGetSymbolAddress((void**)&woh, g_wouth);

    cudaFuncSetAttribute(gemm_qkv96, cudaFuncAttributeMaxDynamicSharedMemorySize, GEMM96_SMEM);
    cudaFuncSetAttribute(gemm_out64, cudaFuncAttributeMaxDynamicSharedMemorySize, OUT64_SMEM);
    cudaFuncSetAttribute(attn_tc,    cudaFuncAttributeMaxDynamicSharedMemorySize, ATTN_SMEM);

    // 0) Fused f32->f16 conversion of all operands, one launch
    to_half3<<<2048, 256>>>(x, xh, w_qkv, wqh, w_out, woh);

    // 1) QKV projection (128x96 tiles, 1024 CTAs)
    gemm_qkv96<<<dim3(32, 32), 256, GEMM96_SMEM>>>(xh, wqh, b_qkv, qh, kh, vh);

    // 2) Causal flash attention (fp16 QK^T + fp16 PV, diag-frag skipping)
    attn_tc<<<dim3(32, 16), 256, ATTN_SMEM>>>(qh, kh, vh, yh);

    // 3) Output projection (128x64 tiles, 512 CTAs -> fine steal granularity)
    gemm_out64<<<dim3(32, 16), 256, OUT64_SMEM>>>(yh, woh, b_out, out);
}

// round 17
// speedup vs baseline: 1.0105x; 1.0105x over previous
#include <cuda_runtime.h>
#include <cuda_fp16.h>
#include <math.h>
#include <cstdint>

// Scratch (allocation-free rule: __device__ globals)
__device__ __half g_qh[4096 * 1024];     // Q fp16 (pre-scaled by 0.125)
__device__ __half g_kh[4096 * 1024];     // K fp16
__device__ __half g_vh[4096 * 1024];     // V fp16
__device__ __half g_yh[4096 * 1024];     // attention output, fp16
__device__ __half g_xh[4096 * 1024];     // fp16 x
__device__ __half g_wqkvh[1024 * 3072];  // fp16 w_qkv
__device__ __half g_wouth[1024 * 1024];  // fp16 w_out

// ---------------------------------------------------------------------------
// Helpers
// ---------------------------------------------------------------------------
__device__ __forceinline__ uint32_t smem_u32(const void* p) {
    uint32_t a;
    asm("{ .reg .u64 t; cvta.to.shared.u64 t, %1; cvt.u32.u64 %0, t; }"
        : "=r"(a) : "l"(p));
    return a;
}
__device__ __forceinline__ void cp_async16(uint32_t dst, const void* src) {
    asm volatile("cp.async.cg.shared.global [%0], [%1], 16;" :: "r"(dst), "l"(src));
}
__device__ __forceinline__ void cp_commit() {
    asm volatile("cp.async.commit_group;");
}
__device__ __forceinline__ void mma_f16_16x8x16(
    float* c, const uint32_t* a, const uint32_t* b) {
    asm volatile(
        "mma.sync.aligned.m16n8k16.row.col.f32.f16.f16.f32 "
        "{%0,%1,%2,%3}, {%4,%5,%6,%7}, {%8,%9}, {%0,%1,%2,%3};"
        : "+f"(c[0]), "+f"(c[1]), "+f"(c[2]), "+f"(c[3])
        : "r"(a[0]), "r"(a[1]), "r"(a[2]), "r"(a[3]), "r"(b[0]), "r"(b[1]));
}
__device__ __forceinline__ void ldmx4(uint32_t* r, uint32_t addr) {
    asm volatile("ldmatrix.sync.aligned.m8n8.x4.shared.b16 {%0,%1,%2,%3}, [%4];"
        : "=r"(r[0]), "=r"(r[1]), "=r"(r[2]), "=r"(r[3]) : "r"(addr));
}
__device__ __forceinline__ void ldmx4t(uint32_t* r, uint32_t addr) {
    asm volatile("ldmatrix.sync.aligned.m8n8.x4.trans.shared.b16 {%0,%1,%2,%3}, [%4];"
        : "=r"(r[0]), "=r"(r[1]), "=r"(r[2]), "=r"(r[3]) : "r"(addr));
}
// pack(lo, hi) -> b32 half2 {lo in [15:0], hi in [31:16]}
__device__ __forceinline__ uint32_t packh2(float lo, float hi) {
    uint32_t d;
    asm("cvt.rn.f16x2.f32 %0, %1, %2;" : "=r"(d) : "f"(hi), "f"(lo));
    return d;
}
// packed 2^x on half2
__device__ __forceinline__ uint32_t h2ex2(uint32_t x) {
    uint32_t d;
    asm("ex2.approx.f16x2 %0, %1;" : "=r"(d) : "r"(x));
    return d;
}

// ---------------------------------------------------------------------------
// Prepass: f32 -> f16, block-range partitioned (no per-element branching).
// Blocks [0,1024): x (4 iters); [1024,1792): w_qkv (4); [1792,2048): w_out (4).
// ---------------------------------------------------------------------------
#define N4_X  (4096 * 1024 / 4)
#define N4_WQ (1024 * 3072 / 4)
#define N4_WO (1024 * 1024 / 4)

__global__ __launch_bounds__(256) void to_half3(
    const float* __restrict__ x,  __half* __restrict__ dx,
    const float* __restrict__ wq, __half* __restrict__ dwq,
    const float* __restrict__ wo, __half* __restrict__ dwo)
{
    const float* s;
    __half* d;
    int base, stride, count;
    if (blockIdx.x < 1024)      { s = x;  d = dx;  base = blockIdx.x;        stride = 1024 * 256; count = N4_X; }
    else if (blockIdx.x < 1792) { s = wq; d = dwq; base = blockIdx.x - 1024; stride = 768 * 256;  count = N4_WQ; }
    else                        { s = wo; d = dwo; base = blockIdx.x - 1792; stride = 256 * 256;  count = N4_WO; }

    for (int i = base * 256 + threadIdx.x; i < count; i += stride) {
        float4 v = ((const float4*)s)[i];
        uint2 o;
        o.x = packh2(v.x, v.y);
        o.y = packh2(v.z, v.w);
        ((uint2*)d)[i] = o;
    }
}

// ---------------------------------------------------------------------------
// fp16 GEMM, 128x96 CTA tile (QKV path).  Warp grid 4(M)x2(N), warp tile
// 32x48 = 2 mf x 6 nf.  B smem [64][104]h.  Epilogue writes Q (x0.125) /
// K / V f16 planes.
// ---------------------------------------------------------------------------
#define G96A_H (128 * 72)
#define G96B_H (64 * 104)
#define G96S_H (G96A_H + G96B_H)
#define GEMM96_SMEM (3 * G96S_H * 2)        // 95,232 B

__global__ __launch_bounds__(256, 2)
void gemm_qkv96(const __half* __restrict__ A, const __half* __restrict__ B,
                const float* __restrict__ bias,
                __half* qh, __half* kh, __half* vh)
{
    extern __shared__ __align__(16) __half smh[];
    const int K = 1024, N = 3072;

    const int tid = threadIdx.x;
    const int wid = tid >> 5, lane = tid & 31;
    const int m0 = blockIdx.x * 128;
    const int n0 = blockIdx.y * 96;
    const int wm = wid & 3;                  // m offset wm*32
    const int wn = wid >> 2;                 // n offset wn*48

    const uint32_t sbase = smem_u32(smh);

    auto prefetch = [&](int k0, int stage) {
        uint32_t Ad = sbase + stage * G96S_H * 2;
        uint32_t Bd = Ad + G96A_H * 2;
        #pragma unroll
        for (int i = 0; i < 4; i++) {        // A: 128 rows x 8 segs
            int s = tid + i * 256;
            int r = s >> 3, seg = s & 7;
            cp_async16(Ad + (r * 72 + seg * 8) * 2,
                       A + (size_t)(m0 + r) * K + k0 + seg * 8);
        }
        #pragma unroll
        for (int i = 0; i < 3; i++) {        // B: 64 rows x 12 segs = 768
            int s = tid + i * 256;
            int r = s / 12, seg = s % 12;
            cp_async16(Bd + (r * 104 + seg * 8) * 2,
                       B + (size_t)(k0 + r) * N + n0 + seg * 8);
        }
        cp_commit();
    };

    float acc[2][6][4];
    #pragma unroll
    for (int i = 0; i < 2; i++)
        #pragma unroll
        for (int j = 0; j < 6; j++)
            #pragma unroll
            for (int r = 0; r < 4; r++) acc[i][j][r] = 0.f;

    const int NCH = K >> 6;
    prefetch(0, 0);
    prefetch(64, 1);

    const int l15 = lane & 15;
    const uint32_t koff16 = (lane & 16) ? 8 : 0;

    for (int c = 0; c < NCH; c++) {
        if (c == NCH - 1)
            asm volatile("cp.async.wait_group 0;" ::: "memory");
        else
            asm volatile("cp.async.wait_group 1;" ::: "memory");
        __syncthreads();

        if (c + 2 < NCH) prefetch((c + 2) * 64, (c + 2) % 3);

        const uint32_t Asm = sbase + (c % 3) * G96S_H * 2;
        const uint32_t Bsm = Asm + G96A_H * 2;

        #pragma unroll
        for (int ks = 0; ks < 4; ks++) {
            const int kb = ks * 16;
            uint32_t af[2][4], bf[6][2];
            #pragma unroll
            for (int mf = 0; mf < 2; mf++)
                ldmx4(af[mf], Asm + ((wm * 32 + mf * 16 + l15) * 72 + kb + koff16) * 2);
            #pragma unroll
            for (int nfp = 0; nfp < 3; nfp++) {
                uint32_t t[4];
                ldmx4t(t, Bsm + ((kb + l15) * 104 + wn * 48 + nfp * 16 + koff16) * 2);
                bf[2 * nfp][0] = t[0]; bf[2 * nfp][1] = t[1];
                bf[2 * nfp + 1][0] = t[2]; bf[2 * nfp + 1][1] = t[3];
            }
            #pragma unroll
            for (int mf = 0; mf < 2; mf++)
                #pragma unroll
                for (int nf = 0; nf < 6; nf++)
                    mma_f16_16x8x16(acc[mf][nf], af[mf], bf[nf]);
        }
        __syncthreads();
    }

    const int lr = lane >> 2;
    const int lc = lane & 3;
    #pragma unroll
    for (int mf = 0; mf < 2; mf++) {
        int row = m0 + wm * 32 + mf * 16 + lr;
        #pragma unroll
        for (int nf = 0; nf < 6; nf++) {
            int col = n0 + wn * 48 + nf * 8 + 2 * lc;
            float b0 = bias[col], b1 = bias[col + 1];
            float v00 = acc[mf][nf][0] + b0, v01 = acc[mf][nf][1] + b1;
            float v10 = acc[mf][nf][2] + b0, v11 = acc[mf][nf][3] + b1;
            if (col < 1024) {                  // Q plane, fold 1/sqrt(hd)
                *(uint32_t*)&qh[(size_t)row * 1024 + col] =
                    packh2(v00 * 0.125f, v01 * 0.125f);
                *(uint32_t*)&qh[(size_t)(row + 8) * 1024 + col] =
                    packh2(v10 * 0.125f, v11 * 0.125f);
            } else if (col < 2048) {           // K plane
                *(uint32_t*)&kh[(size_t)row * 1024 + col - 1024] = packh2(v00, v01);
                *(uint32_t*)&kh[(size_t)(row + 8) * 1024 + col - 1024] = packh2(v10, v11);
            } else {                           // V plane
                *(uint32_t*)&vh[(size_t)row * 1024 + col - 2048] = packh2(v00, v01);
                *(uint32_t*)&vh[(size_t)(row + 8) * 1024 + col - 2048] = packh2(v10, v11);
            }
        }
    }
}

// ---------------------------------------------------------------------------
// fp16 GEMM 128x128 + bias -> f32 C (out-projection; reverted to the proven
// round-15 shape: 256 CTAs, all resident, 35us).
// ---------------------------------------------------------------------------
#define GA_TILE_H (128 * 72)
#define GB_TILE_H (64 * 136)
#define GSTAGE_H  (GA_TILE_H + GB_TILE_H)
#define GEMM_SMEM (3 * GSTAGE_H * 2)        // 107,520 B

__global__ __launch_bounds__(256, 2)
void gemm_tc(const __half* __restrict__ A, const __half* __restrict__ B,
             const float* __restrict__ bias, float* __restrict__ C,
             int M, int N, int K)
{
    extern __shared__ __align__(16) __half smh[];

    const int tid = threadIdx.x;
    const int wid = tid >> 5, lane = tid & 31;
    const int m0 = blockIdx.x * 128;
    const int n0 = blockIdx.y * 128;
    const int wm = wid & 1;
    const int wn = wid >> 1;

    const uint32_t sbase = smem_u32(smh);

    auto prefetch = [&](int k0, int stage) {
        uint32_t Ad = sbase + stage * GSTAGE_H * 2;
        uint32_t Bd = Ad + GA_TILE_H * 2;
        #pragma unroll
        for (int i = 0; i < 4; i++) {
            int s = tid + i * 256;
            int r = s >> 3, seg = s & 7;
            cp_async16(Ad + (r * 72 + seg * 8) * 2,
                       A + (size_t)(m0 + r) * K + k0 + seg * 8);
        }
        #pragma unroll
        for (int i = 0; i < 4; i++) {
            int s = tid + i * 256;
            int r = s >> 4, seg = s & 15;
            cp_async16(Bd + (r * 136 + seg * 8) * 2,
                       B + (size_t)(k0 + r) * N + n0 + seg * 8);
        }
        cp_commit();
    };

    float acc[4][4][4];
    #pragma unroll
    for (int i = 0; i < 4; i++)
        #pragma unroll
        for (int j = 0; j < 4; j++)
            #pragma unroll
            for (int r = 0; r < 4; r++) acc[i][j][r] = 0.f;

    const int NCH = K >> 6;
    prefetch(0, 0);
    if (NCH > 1) prefetch(64, 1);

    const int l15 = lane & 15;
    const uint32_t koff16 = (lane & 16) ? 8 : 0;

    for (int c = 0; c < NCH; c++) {
        if (c == NCH - 1)
            asm volatile("cp.async.wait_group 0;" ::: "memory");
        else
            asm volatile("cp.async.wait_group 1;" ::: "memory");
        __syncthreads();

        if (c + 2 < NCH) prefetch((c + 2) * 64, (c + 2) % 3);

        const uint32_t Asm = sbase + (c % 3) * GSTAGE_H * 2;
        const uint32_t Bsm = Asm + GA_TILE_H * 2;

        #pragma unroll
        for (int ks = 0; ks < 4; ks++) {
            const int kb = ks * 16;
            uint32_t af[4][4], bf[4][2];
            #pragma unroll
            for (int mf = 0; mf < 4; mf++)
                ldmx4(af[mf], Asm + ((wm * 64 + mf * 16 + l15) * 72 + kb + koff16) * 2);
            #pragma unroll
            for (int nfp = 0; nfp < 2; nfp++) {
                uint32_t t[4];
                ldmx4t(t, Bsm + ((kb + l15) * 136 + wn * 32 + nfp * 16 + koff16) * 2);
                bf[2 * nfp][0] = t[0]; bf[2 * nfp][1] = t[1];
                bf[2 * nfp + 1][0] = t[2]; bf[2 * nfp + 1][1] = t[3];
            }
            #pragma unroll
            for (int mf = 0; mf < 4; mf++)
                #pragma unroll
                for (int nf = 0; nf < 4; nf++)
                    mma_f16_16x8x16(acc[mf][nf], af[mf], bf[nf]);
        }
        __syncthreads();
    }

    const int lr = lane >> 2;
    const int lc = lane & 3;
    #pragma unroll
    for (int mf = 0; mf < 4; mf++) {
        int row = m0 + wm * 64 + mf * 16 + lr;
        #pragma unroll
        for (int nf = 0; nf < 4; nf++) {
            int col = n0 + wn * 32 + nf * 8 + 2 * lc;
            float b0 = bias[col], b1 = bias[col + 1];
            *(float2*)&C[(size_t)row * N + col] =
                make_float2(acc[mf][nf][0] + b0, acc[mf][nf][1] + b1);
            *(float2*)&C[(size_t)(row + 8) * N + col] =
                make_float2(acc[mf][nf][2] + b0, acc[mf][nf][3] + b1);
        }
    }
}

// ---------------------------------------------------------------------------
// Causal flash attention, all-fp16 tensor ops (unchanged from round 15).
// smem halves: Q[128][72], K ring3[64][72], V ring3[64][72] = 73,728 B.
// ---------------------------------------------------------------------------
#define ATTN_SMEM 73728
#define LOG2E 1.4426950408889634f

__global__ __launch_bounds__(256, 2)
void attn_tc(const __half* __restrict__ qh_g, const __half* __restrict__ kh_g,
             const __half* __restrict__ v_g,  __half* __restrict__ y)
{
    extern __shared__ __align__(16) __half smh[];

    const int bh = blockIdx.x;                   // 0..31
    const int qt = 15 - blockIdx.y;              // heavy tiles first
    const int b = bh >> 4, h = bh & 15;
    const int tid = threadIdx.x;
    const int wid = tid >> 5, lane = tid & 31;
    const int lr = lane >> 2, lc = lane & 3;
    const int l15 = lane & 15;
    const uint32_t koff16 = (lane & 16) ? 8 : 0;
    const uint32_t koff8  = (lane & 8)  ? 8 : 0;
    const int l7 = lane & 7;
    const int q0 = qt * 128;
    const int rowbase = b * 2048;
    const int colq = h * 64;

    const uint32_t sbase = smem_u32(smh);
    const uint32_t QA = sbase;                   // 128*72 h
    const uint32_t KA = QA + 128 * 72 * 2;       // 3 x 64*72 h
    const uint32_t VA = KA + 3 * 64 * 72 * 2;    // 3 x 64*72 h

    // Async-load Q tile (own commit group; completed by first wait at kt=0)
    #pragma unroll
    for (int j = 0; j < 4; j++) {
        int s = tid + j * 256;
        int r = s >> 3, seg = s & 7;
        cp_async16(QA + (r * 72 + seg * 8) * 2,
                   qh_g + (size_t)(rowbase + q0 + r) * 1024 + colq + seg * 8);
    }
    cp_commit();

    auto prefetch = [&](int kt) {
        const int buf = kt % 3;
        const uint32_t Kd = KA + buf * (64 * 72 * 2);
        const uint32_t Vd = VA + buf * (64 * 72 * 2);
        #pragma unroll
        for (int j = 0; j < 2; j++) {
            int s = tid + j * 256;
            int r = s >> 3, seg = s & 7;
            size_t g = (size_t)(rowbase + kt * 64 + r) * 1024 + colq + seg * 8;
            cp_async16(Kd + (r * 72 + seg * 8) * 2, kh_g + g);
            cp_async16(Vd + (r * 72 + seg * 8) * 2, v_g  + g);
        }
        cp_commit();
    };

    const int ktmax = 2 * qt + 1;                // >= 1 always
    prefetch(0);
    prefetch(1);

    float m_i[2] = {-INFINITY, -INFINITY};
    float l_i[2] = {0.f, 0.f};
    float acc_o[8][4];
    #pragma unroll
    for (int nf = 0; nf < 8; nf++)
        #pragma unroll
        for (int c = 0; c < 4; c++) acc_o[nf][c] = 0.f;

    const int r_row = 16 * wid + lr;

    for (int kt = 0; kt <= ktmax; kt++) {
        if (kt < ktmax)
            asm volatile("cp.async.wait_group 1;" ::: "memory");
        else
            asm volatile("cp.async.wait_group 0;" ::: "memory");
        __syncthreads();     // tile kt (and Q at kt=0) ready; buf (kt+2)%3 free

        if (kt + 2 <= ktmax) prefetch(kt + 2);

        // Odd diagonal tile: rows < 64 (warps 0-3) are entirely masked.
        if (kt == ktmax && wid < 4) continue;

        // Fragment-level diag limit (warp-uniform).
        const int lim = (kt >= 2 * qt) ? (wid - ((kt - 2 * qt) << 2)) : 3;

        const uint32_t KB = KA + (kt % 3) * (64 * 72 * 2);
        const uint32_t VB = VA + (kt % 3) * (64 * 72 * 2);

        // ---- S = Q K^T : plain fp16, ldmatrix frags ----
        float sacc[8][4];
        #pragma unroll
        for (int nf = 0; nf < 8; nf++)
            #pragma unroll
            for (int c = 0; c < 4; c++) sacc[nf][c] = 0.f;

        #pragma unroll
        for (int ks = 0; ks < 4; ks++) {
            const int kb = ks * 16;
            uint32_t ah[4];
            ldmx4(ah, QA + ((16 * wid + l15) * 72 + kb + koff16) * 2);
            #pragma unroll
            for (int nfp = 0; nfp < 4; nfp++) {
                if (nfp <= lim) {
                    uint32_t bh2[4];
                    ldmx4(bh2, KB + ((16 * nfp + l7 + koff16) * 72 + kb + koff8) * 2);
                    mma_f16_16x8x16(sacc[2 * nfp],     ah, bh2);
                    mma_f16_16x8x16(sacc[2 * nfp + 1], ah, bh2 + 2);
                }
            }
        }

        // ---- Causal mask (only the 2 diagonal k-tiles) ----
        if (kt >= 2 * qt) {
            const int rg = q0 + r_row;
            const int cb0 = kt * 64 + 2 * lc;
            #pragma unroll
            for (int nf = 0; nf < 8; nf++) {
                int c0 = cb0 + 8 * nf;
                if (c0     > rg)     sacc[nf][0] = -INFINITY;
                if (c0 + 1 > rg)     sacc[nf][1] = -INFINITY;
                if (c0     > rg + 8) sacc[nf][2] = -INFINITY;
                if (c0 + 1 > rg + 8) sacc[nf][3] = -INFINITY;
            }
        }

        // ---- Online softmax: max update + packed exp2 ----
        float tm0 = -INFINITY, tm1 = -INFINITY;
        #pragma unroll
        for (int nf = 0; nf < 8; nf++) {
            tm0 = fmaxf(tm0, fmaxf(sacc[nf][0], sacc[nf][1]));
            tm1 = fmaxf(tm1, fmaxf(sacc[nf][2], sacc[nf][3]));
        }
        tm0 = fmaxf(tm0, __shfl_xor_sync(0xffffffffu, tm0, 1));
        tm0 = fmaxf(tm0, __shfl_xor_sync(0xffffffffu, tm0, 2));
        tm1 = fmaxf(tm1, __shfl_xor_sync(0xffffffffu, tm1, 1));
        tm1 = fmaxf(tm1, __shfl_xor_sync(0xffffffffu, tm1, 2));

        const float nm0 = fmaxf(m_i[0], tm0);
        const float nm1 = fmaxf(m_i[1], tm1);
        const float sc0 = __expf(m_i[0] - nm0);
        const float sc1 = __expf(m_i[1] - nm1);
        m_i[0] = nm0;
        m_i[1] = nm1;
        const float nmL0 = nm0 * LOG2E, nmL1 = nm1 * LOG2E;

        // P packed as half2 exp2((s-m)*log2e): this IS the PV A-frag.
        uint32_t pfr[8][2];
        #pragma unroll
        for (int nf = 0; nf < 8; nf++) {
            pfr[nf][0] = h2ex2(packh2(fmaf(sacc[nf][0], LOG2E, -nmL0),
                                      fmaf(sacc[nf][1], LOG2E, -nmL0)));
            pfr[nf][1] = h2ex2(packh2(fmaf(sacc[nf][2], LOG2E, -nmL1),
                                      fmaf(sacc[nf][3], LOG2E, -nmL1)));
        }

        // ---- Row-sum l from the SAME f16 p values, in f32 (FMA pipe) ----
        float rs0 = 0.f, rs1 = 0.f;
        #pragma unroll
        for (int nf = 0; nf < 8; nf++) {
            float2 p0 = __half22float2(*(const __half2*)&pfr[nf][0]);
            float2 p1 = __half22float2(*(const __half2*)&pfr[nf][1]);
            rs0 += p0.x + p0.y;
            rs1 += p1.x + p1.y;
        }
        rs0 += __shfl_xor_sync(0xffffffffu, rs0, 1);
        rs0 += __shfl_xor_sync(0xffffffffu, rs0, 2);
        rs1 += __shfl_xor_sync(0xffffffffu, rs1, 1);
        rs1 += __shfl_xor_sync(0xffffffffu, rs1, 2);
        l_i[0] = l_i[0] * sc0 + rs0;
        l_i[1] = l_i[1] * sc1 + rs1;

        // Rescale O accumulators
        #pragma unroll
        for (int nf = 0; nf < 8; nf++) {
            acc_o[nf][0] *= sc0; acc_o[nf][1] *= sc0;
            acc_o[nf][2] *= sc1; acc_o[nf][3] *= sc1;
        }

        // ---- O += P V  (skip key-chunks with all-zero P on diag tiles) ----
        #pragma unroll
        for (int ks = 0; ks < 4; ks++) {
            if (ks <= lim) {
                uint32_t pa[4];
                pa[0] = pfr[2 * ks][0];
                pa[1] = pfr[2 * ks][1];
                pa[2] = pfr[2 * ks + 1][0];
                pa[3] = pfr[2 * ks + 1][1];
                #pragma unroll
                for (int nfp = 0; nfp < 4; nfp++) {
                    uint32_t tv[4];
                    ldmx4t(tv, VB + ((16 * ks + l7 + koff8) * 72 + 16 * nfp + koff16) * 2);
                    mma_f16_16x8x16(acc_o[2 * nfp],     pa, tv);
                    mma_f16_16x8x16(acc_o[2 * nfp + 1], pa, tv + 2);
                }
            }
        }
    }

    // ---- Epilogue: normalize, store y as f16 (out-proj A operand) ----
    const float il0 = 1.f / l_i[0];
    const float il1 = 1.f / l_i[1];
    const size_t row0 = (size_t)(rowbase + q0 + r_row) * 1024;
    const size_t row1 = row0 + 8 * 1024;
    #pragma unroll
    for (int nf = 0; nf < 8; nf++) {
        int col = colq + 8 * nf + 2 * lc;
        *(uint32_t*)&y[row0 + col] = packh2(acc_o[nf][0] * il0, acc_o[nf][1] * il0);
        *(uint32_t*)&y[row1 + col] = packh2(acc_o[nf][2] * il1, acc_o[nf][3] * il1);
    }
}

// ---------------------------------------------------------------------------
extern "C" void kernel_launch(void* const* d_in, const int* in_sizes, int n_in,
                              void* d_out, int out_size)
{
    const float* x     = (const float*)d_in[0];
    const float* w_qkv = (const float*)d_in[1];
    const float* b_qkv = (const float*)d_in[2];
    const float* w_out = (const float*)d_in[3];
    const float* b_out = (const float*)d_in[4];
    float* out = (float*)d_out;

    __half *qh, *kh, *vh, *yh, *xh, *wqh, *woh;
    cudaGetSymbolAddress((void**)&qh,  g_qh);
    cudaGetSymbolAddress((void**)&kh,  g_kh);
    cudaGetSymbolAddress((void**)&vh,  g_vh);
    cudaGetSymbolAddress((void**)&yh,  g_yh);
    cudaGetSymbolAddress((void**)&xh,  g_xh);
    cudaGetSymbolAddress((void**)&wqh, g_wqkvh);
    cudaGetSymbolAddress((void**)&woh, g_wouth);

    cudaFuncSetAttribute(gemm_qkv96, cudaFuncAttributeMaxDynamicSharedMemorySize, GEMM96_SMEM);
    cudaFuncSetAttribute(gemm_tc,    cudaFuncAttributeMaxDynamicSharedMemorySize, GEMM_SMEM);
    cudaFuncSetAttribute(attn_tc,    cudaFuncAttributeMaxDynamicSharedMemorySize, ATTN_SMEM);

    // 0) f32->f16 conversion of all operands (block-range partitioned)
    to_half3<<<2048, 256>>>(x, xh, w_qkv, wqh, w_out, woh);

    // 1) QKV projection (128x96 tiles, 1024 CTAs)
    gemm_qkv96<<<dim3(32, 32), 256, GEMM96_SMEM>>>(xh, wqh, b_qkv, qh, kh, vh);

    // 2) Causal flash attention (fp16 QK^T + fp16 PV, diag-frag skipping)
    attn_tc<<<dim3(32, 16), 256, ATTN_SMEM>>>(qh, kh, vh, yh);

    // 3) Output projection (128x128 tiles, 256 CTAs — all resident)
    gemm_tc<<<dim3(32, 8), 256, GEMM_SMEM>>>(yh, woh, b_out, out, 4096, 1024, 1024);
}